// round 12
// baseline (speedup 1.0000x reference)
#include <cuda_runtime.h>
#include <cuda_fp16.h>
#include <math.h>
#include <stdint.h>

// Problem constants
#define BATCH 32
#define NV    512
#define NQ    256
#define DMODEL 1024
#define D3    3072
#define NHEAD 8
#define DH    128

// ---------------------------------------------------------------------------
// Scratch (static device globals — allocation-free per harness rules)
// ---------------------------------------------------------------------------
__device__ float g_vmean[BATCH * DMODEL];
__device__ float g_qmean[BATCH * DMODEL];
__device__ float g_gate_v[BATCH * DMODEL];
__device__ float g_gate_q[BATCH * DMODEL];
__device__ __half g_vtran_h[BATCH * NV * D3];
__device__ __half g_qtran_h[BATCH * NQ * D3];
__device__ __half g_Av[BATCH * NV * DMODEL];   // half(v), then half(v+upd)
__device__ __half g_Aq[BATCH * NQ * DMODEL];
__device__ __half g_Wvl[DMODEL * D3];
__device__ __half g_Wql[DMODEL * D3];
__device__ __half g_Wvo[DMODEL * DMODEL];
__device__ __half g_Wqo[DMODEL * DMODEL];

// ---------------------------------------------------------------------------
// PTX helpers
// ---------------------------------------------------------------------------
__device__ __forceinline__ uint32_t smem_u32(const void* p) {
    uint32_t a;
    asm("{ .reg .u64 t; cvta.to.shared.u64 t, %1; cvt.u32.u64 %0, t; }" : "=r"(a) : "l"(p));
    return a;
}
__device__ __forceinline__ void cp_async16(uint32_t dst, const void* src) {
    asm volatile("cp.async.cg.shared.global [%0], [%1], 16;" :: "r"(dst), "l"(src));
}
#define CP_COMMIT() asm volatile("cp.async.commit_group;" ::: "memory")
#define CP_WAIT(n)  asm volatile("cp.async.wait_group %0;" :: "n"(n) : "memory")

__device__ __forceinline__ void ldsm_x4(uint32_t* d, uint32_t addr) {
    asm volatile("ldmatrix.sync.aligned.m8n8.x4.shared.b16 {%0,%1,%2,%3}, [%4];"
                 : "=r"(d[0]), "=r"(d[1]), "=r"(d[2]), "=r"(d[3]) : "r"(addr));
}
__device__ __forceinline__ void ldsm_x2(uint32_t* d, uint32_t addr) {
    asm volatile("ldmatrix.sync.aligned.m8n8.x2.shared.b16 {%0,%1}, [%2];"
                 : "=r"(d[0]), "=r"(d[1]) : "r"(addr));
}
__device__ __forceinline__ void ldsm_x4_t(uint32_t* d, uint32_t addr) {
    asm volatile("ldmatrix.sync.aligned.m8n8.x4.trans.shared.b16 {%0,%1,%2,%3}, [%4];"
                 : "=r"(d[0]), "=r"(d[1]), "=r"(d[2]), "=r"(d[3]) : "r"(addr));
}
__device__ __forceinline__ void mma_f16(float* c, const uint32_t* a, const uint32_t* b) {
    asm volatile(
        "mma.sync.aligned.m16n8k16.row.col.f32.f16.f16.f32 "
        "{%0,%1,%2,%3}, {%4,%5,%6,%7}, {%8,%9}, {%0,%1,%2,%3};"
        : "+f"(c[0]), "+f"(c[1]), "+f"(c[2]), "+f"(c[3])
        : "r"(a[0]), "r"(a[1]), "r"(a[2]), "r"(a[3]), "r"(b[0]), "r"(b[1]));
}

__device__ __forceinline__ void store_pair(float* p, float x, float y) {
    *(float2*)p = make_float2(x, y);
}
__device__ __forceinline__ void store_pair(__half* p, float x, float y) {
    *(__half2*)p = __floats2half2_rn(x, y);
}

// ---------------------------------------------------------------------------
// Combined means: grid (BATCH, 4, 2); z=0 -> v (512 rows), z=1 -> q (256 rows)
// ---------------------------------------------------------------------------
__global__ void mean2_kernel(const float* __restrict__ v, const float* __restrict__ q,
                             float* __restrict__ outv, float* __restrict__ outq) {
    const int z = blockIdx.z;
    const float* x = z ? q : v;
    float* out    = z ? outq : outv;
    const int nrows = z ? NQ : NV;
    int b = blockIdx.x;
    int d = blockIdx.y * 256 + threadIdx.x;
    const float* p = x + (size_t)b * nrows * DMODEL + d;
    float s0 = 0.f, s1 = 0.f, s2 = 0.f, s3 = 0.f;
    for (int n = 0; n < nrows; n += 4) {
        s0 += p[(size_t)(n + 0) * DMODEL];
        s1 += p[(size_t)(n + 1) * DMODEL];
        s2 += p[(size_t)(n + 2) * DMODEL];
        s3 += p[(size_t)(n + 3) * DMODEL];
    }
    out[b * DMODEL + d] = (s0 + s1 + s2 + s3) / (float)nrows;
}

// ---------------------------------------------------------------------------
// Prologue2: one launch doing BOTH gates (blocks 0..511) and ALL six
// fp32->fp16 conversions (blocks 512..). 512 threads/block.
// ---------------------------------------------------------------------------
#define U_AV  (BATCH * NV * DMODEL / 8)
#define U_AQ  (BATCH * NQ * DMODEL / 8)
#define U_WL  (DMODEL * D3 / 8)
#define U_WO  (DMODEL * DMODEL / 8)
#define UC1  (U_AV)
#define UC2  (UC1 + U_AQ)
#define UC3  (UC2 + U_WL)
#define UC4  (UC3 + U_WL)
#define UC5  (UC4 + U_WO)
#define UC6  (UC5 + U_WO)
#define PRO_BLOCKS (512 + UC6 / 512)

__device__ __forceinline__ void conv8(const float* __restrict__ x, __half* __restrict__ y, size_t i) {
    float4 a = *(const float4*)(x + i);
    float4 b = *(const float4*)(x + i + 4);
    __half2 h[4];
    h[0] = __floats2half2_rn(a.x, a.y);
    h[1] = __floats2half2_rn(a.z, a.w);
    h[2] = __floats2half2_rn(b.x, b.y);
    h[3] = __floats2half2_rn(b.z, b.w);
    *(uint4*)(y + i) = *(uint4*)h;
}

__global__ __launch_bounds__(512)
void prologue2(const float* __restrict__ mean_v, const float* __restrict__ mean_q,
               const float* __restrict__ w_v4q, const float* __restrict__ b_v4q,
               const float* __restrict__ w_q4v, const float* __restrict__ b_q4v,
               float* __restrict__ gate_q, float* __restrict__ gate_v,
               const float* __restrict__ v, const float* __restrict__ q,
               const float* __restrict__ wvl, const float* __restrict__ wql,
               const float* __restrict__ wvo, const float* __restrict__ wqo,
               __half* __restrict__ Av, __half* __restrict__ Aq,
               __half* __restrict__ Wvl, __half* __restrict__ Wql,
               __half* __restrict__ Wvo, __half* __restrict__ Wqo) {
    const int blk = blockIdx.x;
    if (blk < 512) {
        const int side = blk >> 8;
        const int rem = blk & 255;
        const int b = rem & 31;
        const int dcol = rem >> 5;
        const float* mean = side ? mean_q : mean_v;
        const float* W    = side ? w_q4v : w_v4q;
        const float* bias = side ? b_q4v : b_v4q;
        float* gate       = side ? gate_v : gate_q;

        __shared__ float sm[DMODEL];
        __shared__ float part[4][128];
        const int l = threadIdx.x & 127;
        const int ks = threadIdx.x >> 7;
        const int d = dcol * 128 + l;
        for (int i = threadIdx.x; i < DMODEL; i += 512) sm[i] = mean[b * DMODEL + i];
        __syncthreads();
        const int k0 = ks * 256;
        float a0 = 0.f, a1 = 0.f, a2 = 0.f, a3 = 0.f;
#pragma unroll 4
        for (int k = 0; k < 256; k += 4) {
            a0 += sm[k0 + k + 0] * __ldg(&W[(size_t)(k0 + k + 0) * DMODEL + d]);
            a1 += sm[k0 + k + 1] * __ldg(&W[(size_t)(k0 + k + 1) * DMODEL + d]);
            a2 += sm[k0 + k + 2] * __ldg(&W[(size_t)(k0 + k + 2) * DMODEL + d]);
            a3 += sm[k0 + k + 3] * __ldg(&W[(size_t)(k0 + k + 3) * DMODEL + d]);
        }
        part[ks][l] = (a0 + a1) + (a2 + a3);
        __syncthreads();
        if (ks == 0) {
            float acc = part[0][l] + part[1][l] + part[2][l] + part[3][l] + bias[d];
            gate[b * DMODEL + d] = 1.0f + 1.0f / (1.0f + __expf(-acc));
        }
    } else {
        const int u = (blk - 512) * 512 + threadIdx.x;
        if (u < UC1)      conv8(v,   Av,  (size_t)u * 8);
        else if (u < UC2) conv8(q,   Aq,  (size_t)(u - UC1) * 8);
        else if (u < UC3) conv8(wvl, Wvl, (size_t)(u - UC2) * 8);
        else if (u < UC4) conv8(wql, Wql, (size_t)(u - UC3) * 8);
        else if (u < UC5) conv8(wvo, Wvo, (size_t)(u - UC4) * 8);
        else              conv8(wqo, Wqo, (size_t)(u - UC5) * 8);
    }
}

// ---------------------------------------------------------------------------
// Merged two-sided fp16 mma GEMM (unchanged from round 11).
// ---------------------------------------------------------------------------
#define GSTAGE 18944
#define GOFF_B 10240
#define MBV (BATCH * NV / 128)
#define MBQ (BATCH * NQ / 128)

template <bool GATE, typename OUT>
__global__ __launch_bounds__(256)
void bmma_gemm2(const __half* __restrict__ Avp, const __half* __restrict__ Bvp,
                const float* __restrict__ biasv, const float* __restrict__ gatev,
                OUT* __restrict__ Cvp,
                const __half* __restrict__ Aqp, const __half* __restrict__ Bqp,
                const float* __restrict__ biasq, const float* __restrict__ gateq,
                OUT* __restrict__ Cqp,
                int N, int K) {
    extern __shared__ __align__(16) char smem[];
    const uint32_t sb = smem_u32(smem);
    const int tid = threadIdx.x;
    const int warp = tid >> 5, lane = tid & 31;
    const int wm = warp & 3, wn = warp >> 2;

    const int by = blockIdx.y;
    const bool qside = (by >= MBV);
    const __half* A = qside ? Aqp : Avp;
    const __half* B = qside ? Bqp : Bvp;
    const float* bias = qside ? biasq : biasv;
    const float* gate = qside ? gateq : gatev;
    OUT* C = qside ? Cqp : Cvp;
    const int rpb = qside ? NQ : NV;
    const int m0 = (qside ? by - MBV : by) * 128;
    const int n0 = blockIdx.x * 128;
    const int NST = K >> 5;

    auto load_stage = [&](int s) {
        const uint32_t buf = sb + (uint32_t)(s % 3) * GSTAGE;
        const int k0 = s * 32;
#pragma unroll
        for (int i = 0; i < 2; i++) {
            int c = tid + i * 256;
            {
                int row = c >> 2, kc = c & 3;
                cp_async16(buf + (uint32_t)(row * 80 + kc * 16),
                           A + ((size_t)(m0 + row) * K + k0 + kc * 8));
            }
            {
                int row = c >> 4, nc = c & 15;
                cp_async16(buf + GOFF_B + (uint32_t)(row * 272 + nc * 16),
                           B + ((size_t)(k0 + row) * N + n0 + nc * 8));
            }
        }
    };

    float acc[2][8][4];
#pragma unroll
    for (int i = 0; i < 2; i++)
#pragma unroll
        for (int j = 0; j < 8; j++)
#pragma unroll
            for (int t = 0; t < 4; t++) acc[i][j][t] = 0.f;

    load_stage(0); CP_COMMIT();
    load_stage(1); CP_COMMIT();

    const int lr = lane & 15;
    const int lc = lane >> 4;
    for (int s = 0; s < NST; s++) {
        if (s + 1 < NST) { CP_WAIT(1); } else { CP_WAIT(0); }
        __syncthreads();
        const uint32_t buf = sb + (uint32_t)(s % 3) * GSTAGE;
#pragma unroll
        for (int ks = 0; ks < 2; ks++) {
            uint32_t ah[2][4];
#pragma unroll
            for (int mi = 0; mi < 2; mi++)
                ldsm_x4(ah[mi], buf + (uint32_t)((wm * 32 + mi * 16 + lr) * 80 + ks * 32 + lc * 16));
            uint32_t bh[8][2];
#pragma unroll
            for (int nio = 0; nio < 4; nio++) {
                uint32_t addr = buf + GOFF_B +
                    (uint32_t)((ks * 16 + lr) * 272 + wn * 128 + nio * 32 + lc * 16);
                uint32_t t4[4];
                ldsm_x4_t(t4, addr);
                bh[nio * 2][0] = t4[0]; bh[nio * 2][1] = t4[1];
                bh[nio * 2 + 1][0] = t4[2]; bh[nio * 2 + 1][1] = t4[3];
            }
#pragma unroll
            for (int mi = 0; mi < 2; mi++)
#pragma unroll
                for (int ni = 0; ni < 8; ni++)
                    mma_f16(acc[mi][ni], ah[mi], bh[ni]);
        }
        if (s + 2 < NST) { load_stage(s + 2); CP_COMMIT(); }
    }

    const int gid = lane >> 2, tig = lane & 3;
    const int b_idx = GATE ? (m0 / rpb) : 0;
#pragma unroll
    for (int mi = 0; mi < 2; mi++) {
        int r = m0 + wm * 32 + mi * 16 + gid;
#pragma unroll
        for (int ni = 0; ni < 8; ni++) {
            int c = n0 + wn * 64 + ni * 8 + tig * 2;
            float g0 = 1.f, g1 = 1.f;
            if (GATE) {
                g0 = gate[b_idx * DMODEL + (c & (DMODEL - 1))];
                g1 = gate[b_idx * DMODEL + ((c + 1) & (DMODEL - 1))];
            }
            float bz0 = bias[c], bz1 = bias[c + 1];
            store_pair(&C[(size_t)r * N + c],
                       fmaxf(acc[mi][ni][0] + bz0, 0.f) * g0,
                       fmaxf(acc[mi][ni][1] + bz1, 0.f) * g1);
            store_pair(&C[(size_t)(r + 8) * N + c],
                       fmaxf(acc[mi][ni][2] + bz0, 0.f) * g0,
                       fmaxf(acc[mi][ni][3] + bz1, 0.f) * g1);
        }
    }
}

// ---------------------------------------------------------------------------
// Merged fp16 attention, 256 threads / 8 warps per 32-q-row block.
// Logits: warp owns an 8-wide k-column strip. PV: warp owns 16 d-columns.
// grid (16, NHEAD, 48): z<32 -> v side (b=z, q0=x*32);
//                       z>=32 -> q side (b=2*(z-32)+(x>>3), q0=(x&7)*32).
// ---------------------------------------------------------------------------
#define QSB  272
#define PSH  520
#define OFF_KVB (32 * QSB)
#define KVBUF   (64 * QSB)
#define OFF_PSB (OFF_KVB + 2 * KVBUF)
#define OFF_RINV (OFF_PSB + 32 * PSH * 2)
#define SMEM_ATT (OFF_RINV + 128)

__global__ __launch_bounds__(256)
void attn16m(const __half* __restrict__ vtran, const float* __restrict__ vres,
             __half* __restrict__ vout,
             const __half* __restrict__ qtran, const float* __restrict__ qres,
             __half* __restrict__ qout) {
    const int z = blockIdx.z;
    const bool qsd = (z >= 32);
    const __half* tran = qsd ? qtran : vtran;
    const float* resid = qsd ? qres : vres;
    __half* outh       = qsd ? qout : vout;
    const int NK    = qsd ? NQ : NV;
    const int NROWS = NK;
    const int b  = qsd ? (z - 32) * 2 + (blockIdx.x >> 3) : z;
    const int q0 = (qsd ? (blockIdx.x & 7) : blockIdx.x) * 32;
    const int NC = NK >> 6;

    extern __shared__ __align__(16) char smem[];
    const uint32_t sb = smem_u32(smem);
    __half* smh = (__half*)smem;
    float* rinv = (float*)(smem + OFF_RINV);

    const int tid = threadIdx.x;
    const int wid = tid >> 5, lane = tid & 31;
    const int lr = lane & 15, lc = lane >> 4;
    const int gid = lane >> 2, tig = lane & 3;
    const int h = blockIdx.y;

    auto ldQ = [&]() {
#pragma unroll
        for (int i = 0; i < 2; i++) {
            int c = tid + i * 256;
            int row = c >> 4, ch = c & 15;
            cp_async16(sb + (uint32_t)(row * QSB + ch * 16),
                       tran + ((size_t)(b * NROWS + q0 + row) * D3 + DMODEL + h * DH + ch * 8));
        }
    };
    auto ldKV = [&](int part, int chunk, int buf) {
#pragma unroll
        for (int i = 0; i < 4; i++) {
            int c = tid + i * 256;
            int row = c >> 4, ch = c & 15;
            cp_async16(sb + OFF_KVB + (uint32_t)(buf * KVBUF + row * QSB + ch * 16),
                       tran + ((size_t)(b * NROWS + chunk * 64 + row) * D3 + part + h * DH + ch * 8));
        }
    };

    // ---------------- phase 1: logits ----------------
    ldQ(); ldKV(0, 0, 0); CP_COMMIT();
    for (int c = 0; c < NC; c++) {
        if (c + 1 < NC) { ldKV(0, c + 1, (c + 1) & 1); CP_COMMIT(); CP_WAIT(1); }
        else           { CP_WAIT(0); }
        __syncthreads();
        const uint32_t kb = sb + OFF_KVB + (uint32_t)((c & 1) * KVBUF);
        float acc[2][4];
#pragma unroll
        for (int mi = 0; mi < 2; mi++)
#pragma unroll
            for (int t = 0; t < 4; t++) acc[mi][t] = 0.f;
#pragma unroll
        for (int ks = 0; ks < 8; ks++) {
            uint32_t a[2][4];
            ldsm_x4(a[0], sb + (uint32_t)(lr * QSB + ks * 32 + lc * 16));
            ldsm_x4(a[1], sb + (uint32_t)((16 + lr) * QSB + ks * 32 + lc * 16));
            // B frag (n8k16) for k-cols [wid*8, wid*8+8)
            uint32_t bfr[2];
            ldsm_x2(bfr, kb + (uint32_t)((wid * 8 + (lane & 7)) * QSB + ks * 32 + ((lane >> 3) & 1) * 16));
            mma_f16(acc[0], a[0], bfr);
            mma_f16(acc[1], a[1], bfr);
        }
        const float scl = 0.08838834764831845f;   // 1/sqrt(128)
#pragma unroll
        for (int mi = 0; mi < 2; mi++) {
            int col = c * 64 + wid * 8 + tig * 2;
            *(__half2*)(smh + (OFF_PSB / 2) + (mi * 16 + gid) * PSH + col) =
                __floats2half2_rn(acc[mi][0] * scl, acc[mi][1] * scl);
            *(__half2*)(smh + (OFF_PSB / 2) + (mi * 16 + gid + 8) * PSH + col) =
                __floats2half2_rn(acc[mi][2] * scl, acc[mi][3] * scl);
        }
        __syncthreads();
    }

    // kick off V chunk 0 (overlaps softmax)
    ldKV(2 * DMODEL, 0, 0); CP_COMMIT();

    // ---------------- phase 2: softmax (8 threads per row) ----------------
    {
        const int row = tid >> 3, g = tid & 7;
        __half2* pr = (__half2*)(smh + (OFF_PSB / 2) + row * PSH);
        float m = -1e30f;
        for (int i = g; i < NK / 2; i += 8) {
            float2 f = __half22float2(pr[i]);
            m = fmaxf(m, fmaxf(f.x, f.y));
        }
        m = fmaxf(m, __shfl_xor_sync(0xffffffffu, m, 1));
        m = fmaxf(m, __shfl_xor_sync(0xffffffffu, m, 2));
        m = fmaxf(m, __shfl_xor_sync(0xffffffffu, m, 4));
        float s = 0.f;
        for (int i = g; i < NK / 2; i += 8) {
            float2 f = __half22float2(pr[i]);
            float e0 = __expf(f.x - m), e1 = __expf(f.y - m);
            s += e0 + e1;
            pr[i] = __floats2half2_rn(e0, e1);
        }
        s += __shfl_xor_sync(0xffffffffu, s, 1);
        s += __shfl_xor_sync(0xffffffffu, s, 2);
        s += __shfl_xor_sync(0xffffffffu, s, 4);
        if (g == 0) rinv[row] = 1.0f / s;
    }

    // ---------------- phase 3: O = P @ V (warp owns 16 d-cols) ----------------
    float acc[2][2][4];
#pragma unroll
    for (int mi = 0; mi < 2; mi++)
#pragma unroll
        for (int ni = 0; ni < 2; ni++)
#pragma unroll
            for (int t = 0; t < 4; t++) acc[mi][ni][t] = 0.f;

    for (int c = 0; c < NC; c++) {
        if (c + 1 < NC) { ldKV(2 * DMODEL, c + 1, (c + 1) & 1); CP_COMMIT(); CP_WAIT(1); }
        else           { CP_WAIT(0); }
        __syncthreads();
        const uint32_t kb = sb + OFF_KVB + (uint32_t)((c & 1) * KVBUF);
#pragma unroll
        for (int ks = 0; ks < 4; ks++) {
            uint32_t a[2][4];
            ldsm_x4(a[0], sb + OFF_PSB + (uint32_t)(lr * PSH * 2 + (c * 64 + ks * 16 + lc * 8) * 2));
            ldsm_x4(a[1], sb + OFF_PSB + (uint32_t)((16 + lr) * PSH * 2 + (c * 64 + ks * 16 + lc * 8) * 2));
            uint32_t t4[4];
            ldsm_x4_t(t4, kb + (uint32_t)((ks * 16 + lr) * QSB + wid * 32 + lc * 16));
            uint32_t bv0[2] = {t4[0], t4[1]}, bv1[2] = {t4[2], t4[3]};
            mma_f16(acc[0][0], a[0], bv0); mma_f16(acc[0][1], a[0], bv1);
            mma_f16(acc[1][0], a[1], bv0); mma_f16(acc[1][1], a[1], bv1);
        }
        __syncthreads();
    }

    // epilogue: normalize, add residual, write fp16 (feeds output projection)
#pragma unroll
    for (int mi = 0; mi < 2; mi++) {
        int r0 = mi * 16 + gid, r1 = r0 + 8;
        float inv0 = rinv[r0], inv1 = rinv[r1];
#pragma unroll
        for (int ni = 0; ni < 2; ni++) {
            int col = h * DH + wid * 16 + ni * 8 + tig * 2;
            size_t i0 = (size_t)(b * NROWS + q0 + r0) * DMODEL + col;
            size_t i1 = (size_t)(b * NROWS + q0 + r1) * DMODEL + col;
            float2 rv0 = *(const float2*)&resid[i0];
            float2 rv1 = *(const float2*)&resid[i1];
            *(__half2*)&outh[i0] =
                __floats2half2_rn(acc[mi][ni][0] * inv0 + rv0.x, acc[mi][ni][1] * inv0 + rv0.y);
            *(__half2*)&outh[i1] =
                __floats2half2_rn(acc[mi][ni][2] * inv1 + rv1.x, acc[mi][ni][3] * inv1 + rv1.y);
        }
    }
}

// ---------------------------------------------------------------------------
// launch — 5 kernels total
// ---------------------------------------------------------------------------
extern "C" void kernel_launch(void* const* d_in, const int* in_sizes, int n_in,
                              void* d_out, int out_size) {
    const float* v      = (const float*)d_in[0];
    const float* q      = (const float*)d_in[1];
    const float* w_v4q  = (const float*)d_in[2];
    const float* b_v4q  = (const float*)d_in[3];
    const float* w_q4v  = (const float*)d_in[4];
    const float* b_q4v  = (const float*)d_in[5];
    const float* w_vlin = (const float*)d_in[6];
    const float* b_vlin = (const float*)d_in[7];
    const float* w_qlin = (const float*)d_in[8];
    const float* b_qlin = (const float*)d_in[9];
    const float* w_vout = (const float*)d_in[10];
    const float* b_vout = (const float*)d_in[11];
    const float* w_qout = (const float*)d_in[12];
    const float* b_qout = (const float*)d_in[13];

    float* out_v = (float*)d_out;
    float* out_q = out_v + (size_t)BATCH * NV * DMODEL;

    float *p_vmean, *p_qmean, *p_gv, *p_gq;
    cudaGetSymbolAddress((void**)&p_vmean, g_vmean);
    cudaGetSymbolAddress((void**)&p_qmean, g_qmean);
    cudaGetSymbolAddress((void**)&p_gv,    g_gate_v);
    cudaGetSymbolAddress((void**)&p_gq,    g_gate_q);

    __half *vtran, *qtran, *Av, *Aq, *Wvl, *Wql, *Wvo, *Wqo;
    cudaGetSymbolAddress((void**)&vtran, g_vtran_h);
    cudaGetSymbolAddress((void**)&qtran, g_qtran_h);
    cudaGetSymbolAddress((void**)&Av, g_Av);
    cudaGetSymbolAddress((void**)&Aq, g_Aq);
    cudaGetSymbolAddress((void**)&Wvl, g_Wvl);
    cudaGetSymbolAddress((void**)&Wql, g_Wql);
    cudaGetSymbolAddress((void**)&Wvo, g_Wvo);
    cudaGetSymbolAddress((void**)&Wqo, g_Wqo);

    const int SMEM_G = 3 * GSTAGE;
    cudaFuncSetAttribute((const void*)bmma_gemm2<true, __half>, cudaFuncAttributeMaxDynamicSharedMemorySize, SMEM_G);
    cudaFuncSetAttribute((const void*)bmma_gemm2<false, float>, cudaFuncAttributeMaxDynamicSharedMemorySize, SMEM_G);
    cudaFuncSetAttribute((const void*)attn16m, cudaFuncAttributeMaxDynamicSharedMemorySize, SMEM_ATT);

    // 1) means (both sides)
    mean2_kernel<<<dim3(BATCH, 4, 2), 256>>>(v, q, p_vmean, p_qmean);

    // 2) gates + all conversions (one launch)
    prologue2<<<PRO_BLOCKS, 512>>>(p_vmean, p_qmean, w_v4q, b_v4q, w_q4v, b_q4v,
                                   p_gq, p_gv, v, q, w_vlin, w_qlin, w_vout, w_qout,
                                   Av, Aq, Wvl, Wql, Wvo, Wqo);

    // 3) gated tran projections (both sides, one launch) -> fp16 tran
    bmma_gemm2<true, __half><<<dim3(D3 / 128, MBV + MBQ), 256, SMEM_G>>>(
        Av, Wvl, b_vlin, p_gv, vtran,
        Aq, Wql, b_qlin, p_gq, qtran, D3, DMODEL);

    // 4) attention with fused residual (both sides, one launch, packed grid)
    attn16m<<<dim3(NV / 32, NHEAD, 48), 256, SMEM_ATT>>>(vtran, v, Av, qtran, q, Aq);

    // 5) output projections (both sides, one launch)
    bmma_gemm2<false, float><<<dim3(DMODEL / 128, MBV + MBQ), 256, SMEM_G>>>(
        Av, Wvo, b_vout, nullptr, out_v,
        Aq, Wqo, b_qout, nullptr, out_q, DMODEL, DMODEL);
}

// round 15
// speedup vs baseline: 1.0448x; 1.0448x over previous
#include <cuda_runtime.h>
#include <cuda_fp16.h>
#include <math.h>
#include <stdint.h>

// Problem constants
#define BATCH 32
#define NV    512
#define NQ    256
#define DMODEL 1024
#define D3    3072
#define NHEAD 8
#define DH    128

// ---------------------------------------------------------------------------
// Scratch (static device globals — allocation-free per harness rules)
// ---------------------------------------------------------------------------
__device__ float g_vmean[BATCH * DMODEL];
__device__ float g_qmean[BATCH * DMODEL];
__device__ float g_gate_v[BATCH * DMODEL];
__device__ float g_gate_q[BATCH * DMODEL];
__device__ __half g_vtran_h[BATCH * NV * D3];
__device__ __half g_qtran_h[BATCH * NQ * D3];
__device__ __half g_Av[BATCH * NV * DMODEL];   // half(v), then half(v+upd)
__device__ __half g_Aq[BATCH * NQ * DMODEL];
__device__ __half g_Wvl[DMODEL * D3];
__device__ __half g_Wql[DMODEL * D3];
__device__ __half g_Wvo[DMODEL * DMODEL];
__device__ __half g_Wqo[DMODEL * DMODEL];

// ---------------------------------------------------------------------------
// PTX helpers
// ---------------------------------------------------------------------------
__device__ __forceinline__ uint32_t smem_u32(const void* p) {
    uint32_t a;
    asm("{ .reg .u64 t; cvta.to.shared.u64 t, %1; cvt.u32.u64 %0, t; }" : "=r"(a) : "l"(p));
    return a;
}
__device__ __forceinline__ void cp_async16(uint32_t dst, const void* src) {
    asm volatile("cp.async.cg.shared.global [%0], [%1], 16;" :: "r"(dst), "l"(src));
}
#define CP_COMMIT() asm volatile("cp.async.commit_group;" ::: "memory")
#define CP_WAIT(n)  asm volatile("cp.async.wait_group %0;" :: "n"(n) : "memory")

__device__ __forceinline__ void ldsm_x4(uint32_t* d, uint32_t addr) {
    asm volatile("ldmatrix.sync.aligned.m8n8.x4.shared.b16 {%0,%1,%2,%3}, [%4];"
                 : "=r"(d[0]), "=r"(d[1]), "=r"(d[2]), "=r"(d[3]) : "r"(addr));
}
__device__ __forceinline__ void ldsm_x4_t(uint32_t* d, uint32_t addr) {
    asm volatile("ldmatrix.sync.aligned.m8n8.x4.trans.shared.b16 {%0,%1,%2,%3}, [%4];"
                 : "=r"(d[0]), "=r"(d[1]), "=r"(d[2]), "=r"(d[3]) : "r"(addr));
}
__device__ __forceinline__ void mma_f16(float* c, const uint32_t* a, const uint32_t* b) {
    asm volatile(
        "mma.sync.aligned.m16n8k16.row.col.f32.f16.f16.f32 "
        "{%0,%1,%2,%3}, {%4,%5,%6,%7}, {%8,%9}, {%0,%1,%2,%3};"
        : "+f"(c[0]), "+f"(c[1]), "+f"(c[2]), "+f"(c[3])
        : "r"(a[0]), "r"(a[1]), "r"(a[2]), "r"(a[3]), "r"(b[0]), "r"(b[1]));
}

__device__ __forceinline__ void store_pair(float* p, float x, float y) {
    *(float2*)p = make_float2(x, y);
}
__device__ __forceinline__ void store_pair(__half* p, float x, float y) {
    *(__half2*)p = __floats2half2_rn(x, y);
}

// ---------------------------------------------------------------------------
// Combined means: grid (BATCH, 4, 2); z=0 -> v (512 rows), z=1 -> q (256 rows)
// ---------------------------------------------------------------------------
__global__ void mean2_kernel(const float* __restrict__ v, const float* __restrict__ q,
                             float* __restrict__ outv, float* __restrict__ outq) {
    const int z = blockIdx.z;
    const float* x = z ? q : v;
    float* out    = z ? outq : outv;
    const int nrows = z ? NQ : NV;
    int b = blockIdx.x;
    int d = blockIdx.y * 256 + threadIdx.x;
    const float* p = x + (size_t)b * nrows * DMODEL + d;
    float s0 = 0.f, s1 = 0.f, s2 = 0.f, s3 = 0.f;
    for (int n = 0; n < nrows; n += 4) {
        s0 += p[(size_t)(n + 0) * DMODEL];
        s1 += p[(size_t)(n + 1) * DMODEL];
        s2 += p[(size_t)(n + 2) * DMODEL];
        s3 += p[(size_t)(n + 3) * DMODEL];
    }
    out[b * DMODEL + d] = (s0 + s1 + s2 + s3) / (float)nrows;
}

// ---------------------------------------------------------------------------
// Prologue2: one launch doing BOTH gates (blocks 0..511) and ALL six
// fp32->fp16 conversions (blocks 512..). 512 threads/block.
// ---------------------------------------------------------------------------
#define U_AV  (BATCH * NV * DMODEL / 8)
#define U_AQ  (BATCH * NQ * DMODEL / 8)
#define U_WL  (DMODEL * D3 / 8)
#define U_WO  (DMODEL * DMODEL / 8)
#define UC1  (U_AV)
#define UC2  (UC1 + U_AQ)
#define UC3  (UC2 + U_WL)
#define UC4  (UC3 + U_WL)
#define UC5  (UC4 + U_WO)
#define UC6  (UC5 + U_WO)
#define PRO_BLOCKS (512 + UC6 / 512)

__device__ __forceinline__ void conv8(const float* __restrict__ x, __half* __restrict__ y, size_t i) {
    float4 a = *(const float4*)(x + i);
    float4 b = *(const float4*)(x + i + 4);
    __half2 h[4];
    h[0] = __floats2half2_rn(a.x, a.y);
    h[1] = __floats2half2_rn(a.z, a.w);
    h[2] = __floats2half2_rn(b.x, b.y);
    h[3] = __floats2half2_rn(b.z, b.w);
    *(uint4*)(y + i) = *(uint4*)h;
}

__global__ __launch_bounds__(512)
void prologue2(const float* __restrict__ mean_v, const float* __restrict__ mean_q,
               const float* __restrict__ w_v4q, const float* __restrict__ b_v4q,
               const float* __restrict__ w_q4v, const float* __restrict__ b_q4v,
               float* __restrict__ gate_q, float* __restrict__ gate_v,
               const float* __restrict__ v, const float* __restrict__ q,
               const float* __restrict__ wvl, const float* __restrict__ wql,
               const float* __restrict__ wvo, const float* __restrict__ wqo,
               __half* __restrict__ Av, __half* __restrict__ Aq,
               __half* __restrict__ Wvl, __half* __restrict__ Wql,
               __half* __restrict__ Wvo, __half* __restrict__ Wqo) {
    const int blk = blockIdx.x;
    if (blk < 512) {
        const int side = blk >> 8;
        const int rem = blk & 255;
        const int b = rem & 31;
        const int dcol = rem >> 5;
        const float* mean = side ? mean_q : mean_v;
        const float* W    = side ? w_q4v : w_v4q;
        const float* bias = side ? b_q4v : b_v4q;
        float* gate       = side ? gate_v : gate_q;

        __shared__ float sm[DMODEL];
        __shared__ float part[4][128];
        const int l = threadIdx.x & 127;
        const int ks = threadIdx.x >> 7;
        const int d = dcol * 128 + l;
        for (int i = threadIdx.x; i < DMODEL; i += 512) sm[i] = mean[b * DMODEL + i];
        __syncthreads();
        const int k0 = ks * 256;
        float a0 = 0.f, a1 = 0.f, a2 = 0.f, a3 = 0.f;
#pragma unroll 4
        for (int k = 0; k < 256; k += 4) {
            a0 += sm[k0 + k + 0] * __ldg(&W[(size_t)(k0 + k + 0) * DMODEL + d]);
            a1 += sm[k0 + k + 1] * __ldg(&W[(size_t)(k0 + k + 1) * DMODEL + d]);
            a2 += sm[k0 + k + 2] * __ldg(&W[(size_t)(k0 + k + 2) * DMODEL + d]);
            a3 += sm[k0 + k + 3] * __ldg(&W[(size_t)(k0 + k + 3) * DMODEL + d]);
        }
        part[ks][l] = (a0 + a1) + (a2 + a3);
        __syncthreads();
        if (ks == 0) {
            float acc = part[0][l] + part[1][l] + part[2][l] + part[3][l] + bias[d];
            gate[b * DMODEL + d] = 1.0f + 1.0f / (1.0f + __expf(-acc));
        }
    } else {
        const int u = (blk - 512) * 512 + threadIdx.x;
        if (u < UC1)      conv8(v,   Av,  (size_t)u * 8);
        else if (u < UC2) conv8(q,   Aq,  (size_t)(u - UC1) * 8);
        else if (u < UC3) conv8(wvl, Wvl, (size_t)(u - UC2) * 8);
        else if (u < UC4) conv8(wql, Wql, (size_t)(u - UC3) * 8);
        else if (u < UC5) conv8(wvo, Wvo, (size_t)(u - UC4) * 8);
        else              conv8(wqo, Wqo, (size_t)(u - UC5) * 8);
    }
}

// ---------------------------------------------------------------------------
// Merged two-sided fp16 mma GEMM (unchanged).
// ---------------------------------------------------------------------------
#define GSTAGE 18944
#define GOFF_B 10240
#define MBV (BATCH * NV / 128)
#define MBQ (BATCH * NQ / 128)

template <bool GATE, typename OUT>
__global__ __launch_bounds__(256)
void bmma_gemm2(const __half* __restrict__ Avp, const __half* __restrict__ Bvp,
                const float* __restrict__ biasv, const float* __restrict__ gatev,
                OUT* __restrict__ Cvp,
                const __half* __restrict__ Aqp, const __half* __restrict__ Bqp,
                const float* __restrict__ biasq, const float* __restrict__ gateq,
                OUT* __restrict__ Cqp,
                int N, int K) {
    extern __shared__ __align__(16) char smem[];
    const uint32_t sb = smem_u32(smem);
    const int tid = threadIdx.x;
    const int warp = tid >> 5, lane = tid & 31;
    const int wm = warp & 3, wn = warp >> 2;

    const int by = blockIdx.y;
    const bool qside = (by >= MBV);
    const __half* A = qside ? Aqp : Avp;
    const __half* B = qside ? Bqp : Bvp;
    const float* bias = qside ? biasq : biasv;
    const float* gate = qside ? gateq : gatev;
    OUT* C = qside ? Cqp : Cvp;
    const int rpb = qside ? NQ : NV;
    const int m0 = (qside ? by - MBV : by) * 128;
    const int n0 = blockIdx.x * 128;
    const int NST = K >> 5;

    auto load_stage = [&](int s) {
        const uint32_t buf = sb + (uint32_t)(s % 3) * GSTAGE;
        const int k0 = s * 32;
#pragma unroll
        for (int i = 0; i < 2; i++) {
            int c = tid + i * 256;
            {
                int row = c >> 2, kc = c & 3;
                cp_async16(buf + (uint32_t)(row * 80 + kc * 16),
                           A + ((size_t)(m0 + row) * K + k0 + kc * 8));
            }
            {
                int row = c >> 4, nc = c & 15;
                cp_async16(buf + GOFF_B + (uint32_t)(row * 272 + nc * 16),
                           B + ((size_t)(k0 + row) * N + n0 + nc * 8));
            }
        }
    };

    float acc[2][8][4];
#pragma unroll
    for (int i = 0; i < 2; i++)
#pragma unroll
        for (int j = 0; j < 8; j++)
#pragma unroll
            for (int t = 0; t < 4; t++) acc[i][j][t] = 0.f;

    load_stage(0); CP_COMMIT();
    load_stage(1); CP_COMMIT();

    const int lr = lane & 15;
    const int lc = lane >> 4;
    for (int s = 0; s < NST; s++) {
        if (s + 1 < NST) { CP_WAIT(1); } else { CP_WAIT(0); }
        __syncthreads();
        const uint32_t buf = sb + (uint32_t)(s % 3) * GSTAGE;
#pragma unroll
        for (int ks = 0; ks < 2; ks++) {
            uint32_t ah[2][4];
#pragma unroll
            for (int mi = 0; mi < 2; mi++)
                ldsm_x4(ah[mi], buf + (uint32_t)((wm * 32 + mi * 16 + lr) * 80 + ks * 32 + lc * 16));
            uint32_t bh[8][2];
#pragma unroll
            for (int nio = 0; nio < 4; nio++) {
                uint32_t addr = buf + GOFF_B +
                    (uint32_t)((ks * 16 + lr) * 272 + wn * 128 + nio * 32 + lc * 16);
                uint32_t t4[4];
                ldsm_x4_t(t4, addr);
                bh[nio * 2][0] = t4[0]; bh[nio * 2][1] = t4[1];
                bh[nio * 2 + 1][0] = t4[2]; bh[nio * 2 + 1][1] = t4[3];
            }
#pragma unroll
            for (int mi = 0; mi < 2; mi++)
#pragma unroll
                for (int ni = 0; ni < 8; ni++)
                    mma_f16(acc[mi][ni], ah[mi], bh[ni]);
        }
        if (s + 2 < NST) { load_stage(s + 2); CP_COMMIT(); }
    }

    const int gid = lane >> 2, tig = lane & 3;
    const int b_idx = GATE ? (m0 / rpb) : 0;
#pragma unroll
    for (int mi = 0; mi < 2; mi++) {
        int r = m0 + wm * 32 + mi * 16 + gid;
#pragma unroll
        for (int ni = 0; ni < 8; ni++) {
            int c = n0 + wn * 64 + ni * 8 + tig * 2;
            float g0 = 1.f, g1 = 1.f;
            if (GATE) {
                g0 = gate[b_idx * DMODEL + (c & (DMODEL - 1))];
                g1 = gate[b_idx * DMODEL + ((c + 1) & (DMODEL - 1))];
            }
            float bz0 = bias[c], bz1 = bias[c + 1];
            store_pair(&C[(size_t)r * N + c],
                       fmaxf(acc[mi][ni][0] + bz0, 0.f) * g0,
                       fmaxf(acc[mi][ni][1] + bz1, 0.f) * g1);
            store_pair(&C[(size_t)(r + 8) * N + c],
                       fmaxf(acc[mi][ni][2] + bz0, 0.f) * g0,
                       fmaxf(acc[mi][ni][3] + bz1, 0.f) * g1);
        }
    }
}

// ---------------------------------------------------------------------------
// Merged fp16 attention — 128 threads / 4 warps with Q-fragment hoisting
// (Q frags loaded once during chunk 0, reused across all K chunks).
// PV epilogue column mapping: warp owns 32 d-halves (wid*32), matching the
// V-fragment loads at byte offset wid*64 (= 32 halves).
// Packed grid (16, NHEAD, 48): z<32 -> v side (b=z, q0=x*32);
//                              z>=32 -> q side (b=2*(z-32)+(x>>3), q0=(x&7)*32).
// ---------------------------------------------------------------------------
#define QSB  272
#define PSH  520
#define OFF_KVB (32 * QSB)
#define KVBUF   (64 * QSB)
#define OFF_PSB (OFF_KVB + 2 * KVBUF)
#define OFF_RINV (OFF_PSB + 32 * PSH * 2)
#define SMEM_ATT (OFF_RINV + 128)

__global__ __launch_bounds__(128)
void attn16m(const __half* __restrict__ vtran, const float* __restrict__ vres,
             __half* __restrict__ vout,
             const __half* __restrict__ qtran, const float* __restrict__ qres,
             __half* __restrict__ qout) {
    const int z = blockIdx.z;
    const bool qsd = (z >= 32);
    const __half* tran = qsd ? qtran : vtran;
    const float* resid = qsd ? qres : vres;
    __half* outh       = qsd ? qout : vout;
    const int NK    = qsd ? NQ : NV;
    const int NROWS = NK;
    const int b  = qsd ? (z - 32) * 2 + (blockIdx.x >> 3) : z;
    const int q0 = (qsd ? (blockIdx.x & 7) : blockIdx.x) * 32;
    const int NC = NK >> 6;

    extern __shared__ __align__(16) char smem[];
    const uint32_t sb = smem_u32(smem);
    __half* smh = (__half*)smem;
    float* rinv = (float*)(smem + OFF_RINV);

    const int tid = threadIdx.x;
    const int wid = tid >> 5, lane = tid & 31;
    const int lr = lane & 15, lc = lane >> 4;
    const int gid = lane >> 2, tig = lane & 3;
    const int h = blockIdx.y;

    auto ldQ = [&]() {
#pragma unroll
        for (int i = 0; i < 4; i++) {
            int c = tid + i * 128;
            int row = c >> 4, ch = c & 15;
            cp_async16(sb + (uint32_t)(row * QSB + ch * 16),
                       tran + ((size_t)(b * NROWS + q0 + row) * D3 + DMODEL + h * DH + ch * 8));
        }
    };
    auto ldKV = [&](int part, int chunk, int buf) {
#pragma unroll
        for (int i = 0; i < 8; i++) {
            int c = tid + i * 128;
            int row = c >> 4, ch = c & 15;
            cp_async16(sb + OFF_KVB + (uint32_t)(buf * KVBUF + row * QSB + ch * 16),
                       tran + ((size_t)(b * NROWS + chunk * 64 + row) * D3 + part + h * DH + ch * 8));
        }
    };

    // ---------------- phase 1: logits ----------------
    uint32_t qf[8][2][4];   // hoisted Q fragments: [ks][mi][frag]
    ldQ(); ldKV(0, 0, 0); CP_COMMIT();
    for (int c = 0; c < NC; c++) {
        if (c + 1 < NC) { ldKV(0, c + 1, (c + 1) & 1); CP_COMMIT(); CP_WAIT(1); }
        else           { CP_WAIT(0); }
        __syncthreads();
        const uint32_t kb = sb + OFF_KVB + (uint32_t)((c & 1) * KVBUF);
        float acc[2][2][4];
#pragma unroll
        for (int mi = 0; mi < 2; mi++)
#pragma unroll
            for (int ni = 0; ni < 2; ni++)
#pragma unroll
                for (int t = 0; t < 4; t++) acc[mi][ni][t] = 0.f;
#pragma unroll
        for (int ks = 0; ks < 8; ks++) {
            if (c == 0) {   // load Q frags once; reuse on later chunks
                ldsm_x4(qf[ks][0], sb + (uint32_t)(lr * QSB + ks * 32 + lc * 16));
                ldsm_x4(qf[ks][1], sb + (uint32_t)((16 + lr) * QSB + ks * 32 + lc * 16));
            }
            uint32_t r4[4];
            ldsm_x4(r4, kb + (uint32_t)((wid * 16 + lr) * QSB + ks * 32 + lc * 16));
            uint32_t b0[2] = {r4[0], r4[2]}, b1[2] = {r4[1], r4[3]};
            mma_f16(acc[0][0], qf[ks][0], b0); mma_f16(acc[0][1], qf[ks][0], b1);
            mma_f16(acc[1][0], qf[ks][1], b0); mma_f16(acc[1][1], qf[ks][1], b1);
        }
        const float scl = 0.08838834764831845f;   // 1/sqrt(128)
#pragma unroll
        for (int mi = 0; mi < 2; mi++)
#pragma unroll
            for (int ni = 0; ni < 2; ni++) {
                int col = c * 64 + wid * 16 + ni * 8 + tig * 2;
                *(__half2*)(smh + (OFF_PSB / 2) + (mi * 16 + gid) * PSH + col) =
                    __floats2half2_rn(acc[mi][ni][0] * scl, acc[mi][ni][1] * scl);
                *(__half2*)(smh + (OFF_PSB / 2) + (mi * 16 + gid + 8) * PSH + col) =
                    __floats2half2_rn(acc[mi][ni][2] * scl, acc[mi][ni][3] * scl);
            }
        __syncthreads();
    }

    // kick off V chunk 0 (overlaps softmax)
    ldKV(2 * DMODEL, 0, 0); CP_COMMIT();

    // ---------------- phase 2: softmax ----------------
    {
        const int row = tid >> 2, g = tid & 3;
        __half2* pr = (__half2*)(smh + (OFF_PSB / 2) + row * PSH);
        float m = -1e30f;
        for (int i = g; i < NK / 2; i += 4) {
            float2 f = __half22float2(pr[i]);
            m = fmaxf(m, fmaxf(f.x, f.y));
        }
        m = fmaxf(m, __shfl_xor_sync(0xffffffffu, m, 1));
        m = fmaxf(m, __shfl_xor_sync(0xffffffffu, m, 2));
        float s = 0.f;
        for (int i = g; i < NK / 2; i += 4) {
            float2 f = __half22float2(pr[i]);
            float e0 = __expf(f.x - m), e1 = __expf(f.y - m);
            s += e0 + e1;
            pr[i] = __floats2half2_rn(e0, e1);
        }
        s += __shfl_xor_sync(0xffffffffu, s, 1);
        s += __shfl_xor_sync(0xffffffffu, s, 2);
        if (g == 0) rinv[row] = 1.0f / s;
    }

    // ---------------- phase 3: O = P @ V (warp owns 32 d-halves) ----------------
    float acc[2][4][4];
#pragma unroll
    for (int mi = 0; mi < 2; mi++)
#pragma unroll
        for (int ni = 0; ni < 4; ni++)
#pragma unroll
            for (int t = 0; t < 4; t++) acc[mi][ni][t] = 0.f;

    for (int c = 0; c < NC; c++) {
        if (c + 1 < NC) { ldKV(2 * DMODEL, c + 1, (c + 1) & 1); CP_COMMIT(); CP_WAIT(1); }
        else           { CP_WAIT(0); }
        __syncthreads();
        const uint32_t kb = sb + OFF_KVB + (uint32_t)((c & 1) * KVBUF);
#pragma unroll
        for (int ks = 0; ks < 4; ks++) {
            uint32_t a[2][4];
            ldsm_x4(a[0], sb + OFF_PSB + (uint32_t)(lr * PSH * 2 + (c * 64 + ks * 16 + lc * 8) * 2));
            ldsm_x4(a[1], sb + OFF_PSB + (uint32_t)((16 + lr) * PSH * 2 + (c * 64 + ks * 16 + lc * 8) * 2));
            uint32_t bv[4][2];
#pragma unroll
            for (int nio = 0; nio < 2; nio++) {
                uint32_t t4[4];
                ldsm_x4_t(t4, kb + (uint32_t)((ks * 16 + lr) * QSB + wid * 64 + nio * 32 + lc * 16));
                bv[nio * 2][0] = t4[0]; bv[nio * 2][1] = t4[1];
                bv[nio * 2 + 1][0] = t4[2]; bv[nio * 2 + 1][1] = t4[3];
            }
#pragma unroll
            for (int mi = 0; mi < 2; mi++)
#pragma unroll
                for (int ni = 0; ni < 4; ni++)
                    mma_f16(acc[mi][ni], a[mi], bv[ni]);
        }
        __syncthreads();
    }

    // epilogue: normalize, add residual, write fp16 (feeds output projection)
    // col mapping: warp covers halves [wid*32, wid*32+32)  (loads were wid*64 BYTES)
#pragma unroll
    for (int mi = 0; mi < 2; mi++) {
        int r0 = mi * 16 + gid, r1 = r0 + 8;
        float inv0 = rinv[r0], inv1 = rinv[r1];
#pragma unroll
        for (int ni = 0; ni < 4; ni++) {
            int col = h * DH + wid * 32 + ni * 8 + tig * 2;
            size_t i0 = (size_t)(b * NROWS + q0 + r0) * DMODEL + col;
            size_t i1 = (size_t)(b * NROWS + q0 + r1) * DMODEL + col;
            float2 rv0 = *(const float2*)&resid[i0];
            float2 rv1 = *(const float2*)&resid[i1];
            *(__half2*)&outh[i0] =
                __floats2half2_rn(acc[mi][ni][0] * inv0 + rv0.x, acc[mi][ni][1] * inv0 + rv0.y);
            *(__half2*)&outh[i1] =
                __floats2half2_rn(acc[mi][ni][2] * inv1 + rv1.x, acc[mi][ni][3] * inv1 + rv1.y);
        }
    }
}

// ---------------------------------------------------------------------------
// launch — 5 kernels total
// ---------------------------------------------------------------------------
extern "C" void kernel_launch(void* const* d_in, const int* in_sizes, int n_in,
                              void* d_out, int out_size) {
    const float* v      = (const float*)d_in[0];
    const float* q      = (const float*)d_in[1];
    const float* w_v4q  = (const float*)d_in[2];
    const float* b_v4q  = (const float*)d_in[3];
    const float* w_q4v  = (const float*)d_in[4];
    const float* b_q4v  = (const float*)d_in[5];
    const float* w_vlin = (const float*)d_in[6];
    const float* b_vlin = (const float*)d_in[7];
    const float* w_qlin = (const float*)d_in[8];
    const float* b_qlin = (const float*)d_in[9];
    const float* w_vout = (const float*)d_in[10];
    const float* b_vout = (const float*)d_in[11];
    const float* w_qout = (const float*)d_in[12];
    const float* b_qout = (const float*)d_in[13];

    float* out_v = (float*)d_out;
    float* out_q = out_v + (size_t)BATCH * NV * DMODEL;

    float *p_vmean, *p_qmean, *p_gv, *p_gq;
    cudaGetSymbolAddress((void**)&p_vmean, g_vmean);
    cudaGetSymbolAddress((void**)&p_qmean, g_qmean);
    cudaGetSymbolAddress((void**)&p_gv,    g_gate_v);
    cudaGetSymbolAddress((void**)&p_gq,    g_gate_q);

    __half *vtran, *qtran, *Av, *Aq, *Wvl, *Wql, *Wvo, *Wqo;
    cudaGetSymbolAddress((void**)&vtran, g_vtran_h);
    cudaGetSymbolAddress((void**)&qtran, g_qtran_h);
    cudaGetSymbolAddress((void**)&Av, g_Av);
    cudaGetSymbolAddress((void**)&Aq, g_Aq);
    cudaGetSymbolAddress((void**)&Wvl, g_Wvl);
    cudaGetSymbolAddress((void**)&Wql, g_Wql);
    cudaGetSymbolAddress((void**)&Wvo, g_Wvo);
    cudaGetSymbolAddress((void**)&Wqo, g_Wqo);

    const int SMEM_G = 3 * GSTAGE;
    cudaFuncSetAttribute((const void*)bmma_gemm2<true, __half>, cudaFuncAttributeMaxDynamicSharedMemorySize, SMEM_G);
    cudaFuncSetAttribute((const void*)bmma_gemm2<false, float>, cudaFuncAttributeMaxDynamicSharedMemorySize, SMEM_G);
    cudaFuncSetAttribute((const void*)attn16m, cudaFuncAttributeMaxDynamicSharedMemorySize, SMEM_ATT);

    // 1) means (both sides)
    mean2_kernel<<<dim3(BATCH, 4, 2), 256>>>(v, q, p_vmean, p_qmean);

    // 2) gates + all conversions (one launch)
    prologue2<<<PRO_BLOCKS, 512>>>(p_vmean, p_qmean, w_v4q, b_v4q, w_q4v, b_q4v,
                                   p_gq, p_gv, v, q, w_vlin, w_qlin, w_vout, w_qout,
                                   Av, Aq, Wvl, Wql, Wvo, Wqo);

    // 3) gated tran projections (both sides, one launch) -> fp16 tran
    bmma_gemm2<true, __half><<<dim3(D3 / 128, MBV + MBQ), 256, SMEM_G>>>(
        Av, Wvl, b_vlin, p_gv, vtran,
        Aq, Wql, b_qlin, p_gq, qtran, D3, DMODEL);

    // 4) attention with fused residual (both sides, one launch, packed grid)
    attn16m<<<dim3(NV / 32, NHEAD, 48), 128, SMEM_ATT>>>(vtran, v, Av, qtran, q, Aq);

    // 5) output projections (both sides, one launch)
    bmma_gemm2<false, float><<<dim3(DMODEL / 128, MBV + MBQ), 256, SMEM_G>>>(
        Av, Wvo, b_vout, nullptr, out_v,
        Aq, Wqo, b_qout, nullptr, out_q, DMODEL, DMODEL);
}

// round 16
// speedup vs baseline: 1.0885x; 1.0418x over previous
#include <cuda_runtime.h>
#include <cuda_fp16.h>
#include <math.h>
#include <stdint.h>

// Problem constants
#define BATCH 32
#define NV    512
#define NQ    256
#define DMODEL 1024
#define D3    3072
#define NHEAD 8
#define DH    128

// ---------------------------------------------------------------------------
// Scratch (static device globals — allocation-free per harness rules)
// ---------------------------------------------------------------------------
__device__ float g_vmean[BATCH * DMODEL];
__device__ float g_qmean[BATCH * DMODEL];
__device__ float g_gate_v[BATCH * DMODEL];
__device__ float g_gate_q[BATCH * DMODEL];
__device__ __half g_vtran_h[BATCH * NV * D3];
__device__ __half g_qtran_h[BATCH * NQ * D3];
__device__ __half g_Av[BATCH * NV * DMODEL];   // half(v), then half(v+upd)
__device__ __half g_Aq[BATCH * NQ * DMODEL];
__device__ __half g_Wvl[DMODEL * D3];
__device__ __half g_Wql[DMODEL * D3];
__device__ __half g_Wvo[DMODEL * DMODEL];
__device__ __half g_Wqo[DMODEL * DMODEL];

// ---------------------------------------------------------------------------
// PTX helpers
// ---------------------------------------------------------------------------
__device__ __forceinline__ uint32_t smem_u32(const void* p) {
    uint32_t a;
    asm("{ .reg .u64 t; cvta.to.shared.u64 t, %1; cvt.u32.u64 %0, t; }" : "=r"(a) : "l"(p));
    return a;
}
__device__ __forceinline__ void cp_async16(uint32_t dst, const void* src) {
    asm volatile("cp.async.cg.shared.global [%0], [%1], 16;" :: "r"(dst), "l"(src));
}
#define CP_COMMIT() asm volatile("cp.async.commit_group;" ::: "memory")
#define CP_WAIT(n)  asm volatile("cp.async.wait_group %0;" :: "n"(n) : "memory")

__device__ __forceinline__ void ldsm_x4(uint32_t* d, uint32_t addr) {
    asm volatile("ldmatrix.sync.aligned.m8n8.x4.shared.b16 {%0,%1,%2,%3}, [%4];"
                 : "=r"(d[0]), "=r"(d[1]), "=r"(d[2]), "=r"(d[3]) : "r"(addr));
}
__device__ __forceinline__ void ldsm_x4_t(uint32_t* d, uint32_t addr) {
    asm volatile("ldmatrix.sync.aligned.m8n8.x4.trans.shared.b16 {%0,%1,%2,%3}, [%4];"
                 : "=r"(d[0]), "=r"(d[1]), "=r"(d[2]), "=r"(d[3]) : "r"(addr));
}
__device__ __forceinline__ void mma_f16(float* c, const uint32_t* a, const uint32_t* b) {
    asm volatile(
        "mma.sync.aligned.m16n8k16.row.col.f32.f16.f16.f32 "
        "{%0,%1,%2,%3}, {%4,%5,%6,%7}, {%8,%9}, {%0,%1,%2,%3};"
        : "+f"(c[0]), "+f"(c[1]), "+f"(c[2]), "+f"(c[3])
        : "r"(a[0]), "r"(a[1]), "r"(a[2]), "r"(a[3]), "r"(b[0]), "r"(b[1]));
}

__device__ __forceinline__ void store_pair(float* p, float x, float y) {
    *(float2*)p = make_float2(x, y);
}
__device__ __forceinline__ void store_pair(__half* p, float x, float y) {
    *(__half2*)p = __floats2half2_rn(x, y);
}

// ---------------------------------------------------------------------------
// Combined means: grid (BATCH, 4, 2); z=0 -> v (512 rows), z=1 -> q (256 rows)
// ---------------------------------------------------------------------------
__global__ void mean2_kernel(const float* __restrict__ v, const float* __restrict__ q,
                             float* __restrict__ outv, float* __restrict__ outq) {
    const int z = blockIdx.z;
    const float* x = z ? q : v;
    float* out    = z ? outq : outv;
    const int nrows = z ? NQ : NV;
    int b = blockIdx.x;
    int d = blockIdx.y * 256 + threadIdx.x;
    const float* p = x + (size_t)b * nrows * DMODEL + d;
    float s0 = 0.f, s1 = 0.f, s2 = 0.f, s3 = 0.f;
    for (int n = 0; n < nrows; n += 4) {
        s0 += p[(size_t)(n + 0) * DMODEL];
        s1 += p[(size_t)(n + 1) * DMODEL];
        s2 += p[(size_t)(n + 2) * DMODEL];
        s3 += p[(size_t)(n + 3) * DMODEL];
    }
    out[b * DMODEL + d] = (s0 + s1 + s2 + s3) / (float)nrows;
}

// ---------------------------------------------------------------------------
// Prologue2: one launch doing BOTH gates (blocks 0..511) and ALL six
// fp32->fp16 conversions (blocks 512..). 512 threads/block.
// ---------------------------------------------------------------------------
#define U_AV  (BATCH * NV * DMODEL / 8)
#define U_AQ  (BATCH * NQ * DMODEL / 8)
#define U_WL  (DMODEL * D3 / 8)
#define U_WO  (DMODEL * DMODEL / 8)
#define UC1  (U_AV)
#define UC2  (UC1 + U_AQ)
#define UC3  (UC2 + U_WL)
#define UC4  (UC3 + U_WL)
#define UC5  (UC4 + U_WO)
#define UC6  (UC5 + U_WO)
#define PRO_BLOCKS (512 + UC6 / 512)

__device__ __forceinline__ void conv8(const float* __restrict__ x, __half* __restrict__ y, size_t i) {
    float4 a = *(const float4*)(x + i);
    float4 b = *(const float4*)(x + i + 4);
    __half2 h[4];
    h[0] = __floats2half2_rn(a.x, a.y);
    h[1] = __floats2half2_rn(a.z, a.w);
    h[2] = __floats2half2_rn(b.x, b.y);
    h[3] = __floats2half2_rn(b.z, b.w);
    *(uint4*)(y + i) = *(uint4*)h;
}

__global__ __launch_bounds__(512)
void prologue2(const float* __restrict__ mean_v, const float* __restrict__ mean_q,
               const float* __restrict__ w_v4q, const float* __restrict__ b_v4q,
               const float* __restrict__ w_q4v, const float* __restrict__ b_q4v,
               float* __restrict__ gate_q, float* __restrict__ gate_v,
               const float* __restrict__ v, const float* __restrict__ q,
               const float* __restrict__ wvl, const float* __restrict__ wql,
               const float* __restrict__ wvo, const float* __restrict__ wqo,
               __half* __restrict__ Av, __half* __restrict__ Aq,
               __half* __restrict__ Wvl, __half* __restrict__ Wql,
               __half* __restrict__ Wvo, __half* __restrict__ Wqo) {
    const int blk = blockIdx.x;
    if (blk < 512) {
        const int side = blk >> 8;
        const int rem = blk & 255;
        const int b = rem & 31;
        const int dcol = rem >> 5;
        const float* mean = side ? mean_q : mean_v;
        const float* W    = side ? w_q4v : w_v4q;
        const float* bias = side ? b_q4v : b_v4q;
        float* gate       = side ? gate_v : gate_q;

        __shared__ float sm[DMODEL];
        __shared__ float part[4][128];
        const int l = threadIdx.x & 127;
        const int ks = threadIdx.x >> 7;
        const int d = dcol * 128 + l;
        for (int i = threadIdx.x; i < DMODEL; i += 512) sm[i] = mean[b * DMODEL + i];
        __syncthreads();
        const int k0 = ks * 256;
        float a0 = 0.f, a1 = 0.f, a2 = 0.f, a3 = 0.f;
#pragma unroll 4
        for (int k = 0; k < 256; k += 4) {
            a0 += sm[k0 + k + 0] * __ldg(&W[(size_t)(k0 + k + 0) * DMODEL + d]);
            a1 += sm[k0 + k + 1] * __ldg(&W[(size_t)(k0 + k + 1) * DMODEL + d]);
            a2 += sm[k0 + k + 2] * __ldg(&W[(size_t)(k0 + k + 2) * DMODEL + d]);
            a3 += sm[k0 + k + 3] * __ldg(&W[(size_t)(k0 + k + 3) * DMODEL + d]);
        }
        part[ks][l] = (a0 + a1) + (a2 + a3);
        __syncthreads();
        if (ks == 0) {
            float acc = part[0][l] + part[1][l] + part[2][l] + part[3][l] + bias[d];
            gate[b * DMODEL + d] = 1.0f + 1.0f / (1.0f + __expf(-acc));
        }
    } else {
        const int u = (blk - 512) * 512 + threadIdx.x;
        if (u < UC1)      conv8(v,   Av,  (size_t)u * 8);
        else if (u < UC2) conv8(q,   Aq,  (size_t)(u - UC1) * 8);
        else if (u < UC3) conv8(wvl, Wvl, (size_t)(u - UC2) * 8);
        else if (u < UC4) conv8(wql, Wql, (size_t)(u - UC3) * 8);
        else if (u < UC5) conv8(wvo, Wvo, (size_t)(u - UC4) * 8);
        else              conv8(wqo, Wqo, (size_t)(u - UC5) * 8);
    }
}

// ---------------------------------------------------------------------------
// Merged two-sided fp16 mma GEMM (unchanged — at fallback-HMMA pipe floor).
// ---------------------------------------------------------------------------
#define GSTAGE 18944
#define GOFF_B 10240
#define MBV (BATCH * NV / 128)
#define MBQ (BATCH * NQ / 128)

template <bool GATE, typename OUT>
__global__ __launch_bounds__(256)
void bmma_gemm2(const __half* __restrict__ Avp, const __half* __restrict__ Bvp,
                const float* __restrict__ biasv, const float* __restrict__ gatev,
                OUT* __restrict__ Cvp,
                const __half* __restrict__ Aqp, const __half* __restrict__ Bqp,
                const float* __restrict__ biasq, const float* __restrict__ gateq,
                OUT* __restrict__ Cqp,
                int N, int K) {
    extern __shared__ __align__(16) char smem[];
    const uint32_t sb = smem_u32(smem);
    const int tid = threadIdx.x;
    const int warp = tid >> 5, lane = tid & 31;
    const int wm = warp & 3, wn = warp >> 2;

    const int by = blockIdx.y;
    const bool qside = (by >= MBV);
    const __half* A = qside ? Aqp : Avp;
    const __half* B = qside ? Bqp : Bvp;
    const float* bias = qside ? biasq : biasv;
    const float* gate = qside ? gateq : gatev;
    OUT* C = qside ? Cqp : Cvp;
    const int rpb = qside ? NQ : NV;
    const int m0 = (qside ? by - MBV : by) * 128;
    const int n0 = blockIdx.x * 128;
    const int NST = K >> 5;

    auto load_stage = [&](int s) {
        const uint32_t buf = sb + (uint32_t)(s % 3) * GSTAGE;
        const int k0 = s * 32;
#pragma unroll
        for (int i = 0; i < 2; i++) {
            int c = tid + i * 256;
            {
                int row = c >> 2, kc = c & 3;
                cp_async16(buf + (uint32_t)(row * 80 + kc * 16),
                           A + ((size_t)(m0 + row) * K + k0 + kc * 8));
            }
            {
                int row = c >> 4, nc = c & 15;
                cp_async16(buf + GOFF_B + (uint32_t)(row * 272 + nc * 16),
                           B + ((size_t)(k0 + row) * N + n0 + nc * 8));
            }
        }
    };

    float acc[2][8][4];
#pragma unroll
    for (int i = 0; i < 2; i++)
#pragma unroll
        for (int j = 0; j < 8; j++)
#pragma unroll
            for (int t = 0; t < 4; t++) acc[i][j][t] = 0.f;

    load_stage(0); CP_COMMIT();
    load_stage(1); CP_COMMIT();

    const int lr = lane & 15;
    const int lc = lane >> 4;
    for (int s = 0; s < NST; s++) {
        if (s + 1 < NST) { CP_WAIT(1); } else { CP_WAIT(0); }
        __syncthreads();
        const uint32_t buf = sb + (uint32_t)(s % 3) * GSTAGE;
#pragma unroll
        for (int ks = 0; ks < 2; ks++) {
            uint32_t ah[2][4];
#pragma unroll
            for (int mi = 0; mi < 2; mi++)
                ldsm_x4(ah[mi], buf + (uint32_t)((wm * 32 + mi * 16 + lr) * 80 + ks * 32 + lc * 16));
            uint32_t bh[8][2];
#pragma unroll
            for (int nio = 0; nio < 4; nio++) {
                uint32_t addr = buf + GOFF_B +
                    (uint32_t)((ks * 16 + lr) * 272 + wn * 128 + nio * 32 + lc * 16);
                uint32_t t4[4];
                ldsm_x4_t(t4, addr);
                bh[nio * 2][0] = t4[0]; bh[nio * 2][1] = t4[1];
                bh[nio * 2 + 1][0] = t4[2]; bh[nio * 2 + 1][1] = t4[3];
            }
#pragma unroll
            for (int mi = 0; mi < 2; mi++)
#pragma unroll
                for (int ni = 0; ni < 8; ni++)
                    mma_f16(acc[mi][ni], ah[mi], bh[ni]);
        }
        if (s + 2 < NST) { load_stage(s + 2); CP_COMMIT(); }
    }

    const int gid = lane >> 2, tig = lane & 3;
    const int b_idx = GATE ? (m0 / rpb) : 0;
#pragma unroll
    for (int mi = 0; mi < 2; mi++) {
        int r = m0 + wm * 32 + mi * 16 + gid;
#pragma unroll
        for (int ni = 0; ni < 8; ni++) {
            int c = n0 + wn * 64 + ni * 8 + tig * 2;
            float g0 = 1.f, g1 = 1.f;
            if (GATE) {
                g0 = gate[b_idx * DMODEL + (c & (DMODEL - 1))];
                g1 = gate[b_idx * DMODEL + ((c + 1) & (DMODEL - 1))];
            }
            float bz0 = bias[c], bz1 = bias[c + 1];
            store_pair(&C[(size_t)r * N + c],
                       fmaxf(acc[mi][ni][0] + bz0, 0.f) * g0,
                       fmaxf(acc[mi][ni][1] + bz1, 0.f) * g1);
            store_pair(&C[(size_t)(r + 8) * N + c],
                       fmaxf(acc[mi][ni][2] + bz0, 0.f) * g0,
                       fmaxf(acc[mi][ni][3] + bz1, 0.f) * g1);
        }
    }
}

// ---------------------------------------------------------------------------
// Merged fp16 attention — 128 threads / 4 warps with Q-fragment hoisting.
// rinv ALIASES the Q staging region (offset 0): Q smem is dead after logits
// chunk 0 (Q lives in hoisted registers), and every rinv read/write is
// separated from Q use by __syncthreads. This drops SMEM_ATT to 76800 so
// 3 CTAs/SM fit exactly: 3 x (76800 + 1024 reserved) = 233472 = 228 KB.
// Packed grid (16, NHEAD, 48): z<32 -> v side (b=z, q0=x*32);
//                              z>=32 -> q side (b=2*(z-32)+(x>>3), q0=(x&7)*32).
// ---------------------------------------------------------------------------
#define QSB  272
#define PSH  520
#define OFF_KVB (32 * QSB)
#define KVBUF   (64 * QSB)
#define OFF_PSB (OFF_KVB + 2 * KVBUF)
#define SMEM_ATT (OFF_PSB + 32 * PSH * 2)   // 76800

__global__ __launch_bounds__(128)
void attn16m(const __half* __restrict__ vtran, const float* __restrict__ vres,
             __half* __restrict__ vout,
             const __half* __restrict__ qtran, const float* __restrict__ qres,
             __half* __restrict__ qout) {
    const int z = blockIdx.z;
    const bool qsd = (z >= 32);
    const __half* tran = qsd ? qtran : vtran;
    const float* resid = qsd ? qres : vres;
    __half* outh       = qsd ? qout : vout;
    const int NK    = qsd ? NQ : NV;
    const int NROWS = NK;
    const int b  = qsd ? (z - 32) * 2 + (blockIdx.x >> 3) : z;
    const int q0 = (qsd ? (blockIdx.x & 7) : blockIdx.x) * 32;
    const int NC = NK >> 6;

    extern __shared__ __align__(16) char smem[];
    const uint32_t sb = smem_u32(smem);
    __half* smh = (__half*)smem;
    float* rinv = (float*)smem;    // aliases Q staging region (dead after logits chunk 0)

    const int tid = threadIdx.x;
    const int wid = tid >> 5, lane = tid & 31;
    const int lr = lane & 15, lc = lane >> 4;
    const int gid = lane >> 2, tig = lane & 3;
    const int h = blockIdx.y;

    auto ldQ = [&]() {
#pragma unroll
        for (int i = 0; i < 4; i++) {
            int c = tid + i * 128;
            int row = c >> 4, ch = c & 15;
            cp_async16(sb + (uint32_t)(row * QSB + ch * 16),
                       tran + ((size_t)(b * NROWS + q0 + row) * D3 + DMODEL + h * DH + ch * 8));
        }
    };
    auto ldKV = [&](int part, int chunk, int buf) {
#pragma unroll
        for (int i = 0; i < 8; i++) {
            int c = tid + i * 128;
            int row = c >> 4, ch = c & 15;
            cp_async16(sb + OFF_KVB + (uint32_t)(buf * KVBUF + row * QSB + ch * 16),
                       tran + ((size_t)(b * NROWS + chunk * 64 + row) * D3 + part + h * DH + ch * 8));
        }
    };

    // ---------------- phase 1: logits ----------------
    uint32_t qf[8][2][4];   // hoisted Q fragments: [ks][mi][frag]
    ldQ(); ldKV(0, 0, 0); CP_COMMIT();
    for (int c = 0; c < NC; c++) {
        if (c + 1 < NC) { ldKV(0, c + 1, (c + 1) & 1); CP_COMMIT(); CP_WAIT(1); }
        else           { CP_WAIT(0); }
        __syncthreads();
        const uint32_t kb = sb + OFF_KVB + (uint32_t)((c & 1) * KVBUF);
        float acc[2][2][4];
#pragma unroll
        for (int mi = 0; mi < 2; mi++)
#pragma unroll
            for (int ni = 0; ni < 2; ni++)
#pragma unroll
                for (int t = 0; t < 4; t++) acc[mi][ni][t] = 0.f;
#pragma unroll
        for (int ks = 0; ks < 8; ks++) {
            if (c == 0) {   // load Q frags once; reuse on later chunks
                ldsm_x4(qf[ks][0], sb + (uint32_t)(lr * QSB + ks * 32 + lc * 16));
                ldsm_x4(qf[ks][1], sb + (uint32_t)((16 + lr) * QSB + ks * 32 + lc * 16));
            }
            uint32_t r4[4];
            ldsm_x4(r4, kb + (uint32_t)((wid * 16 + lr) * QSB + ks * 32 + lc * 16));
            uint32_t b0[2] = {r4[0], r4[2]}, b1[2] = {r4[1], r4[3]};
            mma_f16(acc[0][0], qf[ks][0], b0); mma_f16(acc[0][1], qf[ks][0], b1);
            mma_f16(acc[1][0], qf[ks][1], b0); mma_f16(acc[1][1], qf[ks][1], b1);
        }
        const float scl = 0.08838834764831845f;   // 1/sqrt(128)
#pragma unroll
        for (int mi = 0; mi < 2; mi++)
#pragma unroll
            for (int ni = 0; ni < 2; ni++) {
                int col = c * 64 + wid * 16 + ni * 8 + tig * 2;
                *(__half2*)(smh + (OFF_PSB / 2) + (mi * 16 + gid) * PSH + col) =
                    __floats2half2_rn(acc[mi][ni][0] * scl, acc[mi][ni][1] * scl);
                *(__half2*)(smh + (OFF_PSB / 2) + (mi * 16 + gid + 8) * PSH + col) =
                    __floats2half2_rn(acc[mi][ni][2] * scl, acc[mi][ni][3] * scl);
            }
        __syncthreads();
    }

    // kick off V chunk 0 (overlaps softmax)
    ldKV(2 * DMODEL, 0, 0); CP_COMMIT();

    // ---------------- phase 2: softmax ----------------
    {
        const int row = tid >> 2, g = tid & 3;
        __half2* pr = (__half2*)(smh + (OFF_PSB / 2) + row * PSH);
        float m = -1e30f;
        for (int i = g; i < NK / 2; i += 4) {
            float2 f = __half22float2(pr[i]);
            m = fmaxf(m, fmaxf(f.x, f.y));
        }
        m = fmaxf(m, __shfl_xor_sync(0xffffffffu, m, 1));
        m = fmaxf(m, __shfl_xor_sync(0xffffffffu, m, 2));
        float s = 0.f;
        for (int i = g; i < NK / 2; i += 4) {
            float2 f = __half22float2(pr[i]);
            float e0 = __expf(f.x - m), e1 = __expf(f.y - m);
            s += e0 + e1;
            pr[i] = __floats2half2_rn(e0, e1);
        }
        s += __shfl_xor_sync(0xffffffffu, s, 1);
        s += __shfl_xor_sync(0xffffffffu, s, 2);
        if (g == 0) rinv[row] = 1.0f / s;
    }

    // ---------------- phase 3: O = P @ V (warp owns 32 d-halves) ----------------
    float acc[2][4][4];
#pragma unroll
    for (int mi = 0; mi < 2; mi++)
#pragma unroll
        for (int ni = 0; ni < 4; ni++)
#pragma unroll
            for (int t = 0; t < 4; t++) acc[mi][ni][t] = 0.f;

    for (int c = 0; c < NC; c++) {
        if (c + 1 < NC) { ldKV(2 * DMODEL, c + 1, (c + 1) & 1); CP_COMMIT(); CP_WAIT(1); }
        else           { CP_WAIT(0); }
        __syncthreads();
        const uint32_t kb = sb + OFF_KVB + (uint32_t)((c & 1) * KVBUF);
#pragma unroll
        for (int ks = 0; ks < 4; ks++) {
            uint32_t a[2][4];
            ldsm_x4(a[0], sb + OFF_PSB + (uint32_t)(lr * PSH * 2 + (c * 64 + ks * 16 + lc * 8) * 2));
            ldsm_x4(a[1], sb + OFF_PSB + (uint32_t)((16 + lr) * PSH * 2 + (c * 64 + ks * 16 + lc * 8) * 2));
            uint32_t bv[4][2];
#pragma unroll
            for (int nio = 0; nio < 2; nio++) {
                uint32_t t4[4];
                ldsm_x4_t(t4, kb + (uint32_t)((ks * 16 + lr) * QSB + wid * 64 + nio * 32 + lc * 16));
                bv[nio * 2][0] = t4[0]; bv[nio * 2][1] = t4[1];
                bv[nio * 2 + 1][0] = t4[2]; bv[nio * 2 + 1][1] = t4[3];
            }
#pragma unroll
            for (int mi = 0; mi < 2; mi++)
#pragma unroll
                for (int ni = 0; ni < 4; ni++)
                    mma_f16(acc[mi][ni], a[mi], bv[ni]);
        }
        __syncthreads();
    }

    // epilogue: normalize, add residual, write fp16 (feeds output projection)
    // col mapping: warp covers halves [wid*32, wid*32+32)  (loads were wid*64 BYTES)
#pragma unroll
    for (int mi = 0; mi < 2; mi++) {
        int r0 = mi * 16 + gid, r1 = r0 + 8;
        float inv0 = rinv[r0], inv1 = rinv[r1];
#pragma unroll
        for (int ni = 0; ni < 4; ni++) {
            int col = h * DH + wid * 32 + ni * 8 + tig * 2;
            size_t i0 = (size_t)(b * NROWS + q0 + r0) * DMODEL + col;
            size_t i1 = (size_t)(b * NROWS + q0 + r1) * DMODEL + col;
            float2 rv0 = *(const float2*)&resid[i0];
            float2 rv1 = *(const float2*)&resid[i1];
            *(__half2*)&outh[i0] =
                __floats2half2_rn(acc[mi][ni][0] * inv0 + rv0.x, acc[mi][ni][1] * inv0 + rv0.y);
            *(__half2*)&outh[i1] =
                __floats2half2_rn(acc[mi][ni][2] * inv1 + rv1.x, acc[mi][ni][3] * inv1 + rv1.y);
        }
    }
}

// ---------------------------------------------------------------------------
// launch — 5 kernels total
// ---------------------------------------------------------------------------
extern "C" void kernel_launch(void* const* d_in, const int* in_sizes, int n_in,
                              void* d_out, int out_size) {
    const float* v      = (const float*)d_in[0];
    const float* q      = (const float*)d_in[1];
    const float* w_v4q  = (const float*)d_in[2];
    const float* b_v4q  = (const float*)d_in[3];
    const float* w_q4v  = (const float*)d_in[4];
    const float* b_q4v  = (const float*)d_in[5];
    const float* w_vlin = (const float*)d_in[6];
    const float* b_vlin = (const float*)d_in[7];
    const float* w_qlin = (const float*)d_in[8];
    const float* b_qlin = (const float*)d_in[9];
    const float* w_vout = (const float*)d_in[10];
    const float* b_vout = (const float*)d_in[11];
    const float* w_qout = (const float*)d_in[12];
    const float* b_qout = (const float*)d_in[13];

    float* out_v = (float*)d_out;
    float* out_q = out_v + (size_t)BATCH * NV * DMODEL;

    float *p_vmean, *p_qmean, *p_gv, *p_gq;
    cudaGetSymbolAddress((void**)&p_vmean, g_vmean);
    cudaGetSymbolAddress((void**)&p_qmean, g_qmean);
    cudaGetSymbolAddress((void**)&p_gv,    g_gate_v);
    cudaGetSymbolAddress((void**)&p_gq,    g_gate_q);

    __half *vtran, *qtran, *Av, *Aq, *Wvl, *Wql, *Wvo, *Wqo;
    cudaGetSymbolAddress((void**)&vtran, g_vtran_h);
    cudaGetSymbolAddress((void**)&qtran, g_qtran_h);
    cudaGetSymbolAddress((void**)&Av, g_Av);
    cudaGetSymbolAddress((void**)&Aq, g_Aq);
    cudaGetSymbolAddress((void**)&Wvl, g_Wvl);
    cudaGetSymbolAddress((void**)&Wql, g_Wql);
    cudaGetSymbolAddress((void**)&Wvo, g_Wvo);
    cudaGetSymbolAddress((void**)&Wqo, g_Wqo);

    const int SMEM_G = 3 * GSTAGE;
    cudaFuncSetAttribute((const void*)bmma_gemm2<true, __half>, cudaFuncAttributeMaxDynamicSharedMemorySize, SMEM_G);
    cudaFuncSetAttribute((const void*)bmma_gemm2<false, float>, cudaFuncAttributeMaxDynamicSharedMemorySize, SMEM_G);
    cudaFuncSetAttribute((const void*)attn16m, cudaFuncAttributeMaxDynamicSharedMemorySize, SMEM_ATT);

    // 1) means (both sides)
    mean2_kernel<<<dim3(BATCH, 4, 2), 256>>>(v, q, p_vmean, p_qmean);

    // 2) gates + all conversions (one launch)
    prologue2<<<PRO_BLOCKS, 512>>>(p_vmean, p_qmean, w_v4q, b_v4q, w_q4v, b_q4v,
                                   p_gq, p_gv, v, q, w_vlin, w_qlin, w_vout, w_qout,
                                   Av, Aq, Wvl, Wql, Wvo, Wqo);

    // 3) gated tran projections (both sides, one launch) -> fp16 tran
    bmma_gemm2<true, __half><<<dim3(D3 / 128, MBV + MBQ), 256, SMEM_G>>>(
        Av, Wvl, b_vlin, p_gv, vtran,
        Aq, Wql, b_qlin, p_gq, qtran, D3, DMODEL);

    // 4) attention with fused residual (both sides, one launch, packed grid)
    attn16m<<<dim3(NV / 32, NHEAD, 48), 128, SMEM_ATT>>>(vtran, v, Av, qtran, q, Aq);

    // 5) output projections (both sides, one launch)
    bmma_gemm2<false, float><<<dim3(DMODEL / 128, MBV + MBQ), 256, SMEM_G>>>(
        Av, Wvo, b_vout, nullptr, out_v,
        Aq, Wqo, b_qout, nullptr, out_q, DMODEL, DMODEL);
}